// round 12
// baseline (speedup 1.0000x reference)
#include <cuda_runtime.h>
#include <cuda_fp16.h>
#include <cstdint>

typedef uint32_t u32;

#define IN_C  256
#define OUT_C 256
#define HW    32
#define NB    64
#define NPIX  1024

__device__ int g_y[NB];
__device__ int g_arc[NB];
__device__ int g_order[NB];
// fragment-packed fp16 weights: [br][rs][chunk8][tile16][ks2][lane32][4 words]
__device__ u32 g_wf[2752512];
// repacked fp16 x: [b][pix][chunk8][ks2][slot8] words; slot order cp(0,4,1,5,2,6,3,7)
__device__ u32 g_xb[8388608];

__constant__ int c_woffw[4] = {0, 32768, 327680, 1146880};

// ---------------- helpers ----------------
__device__ __forceinline__ u32 smem_u32(const void* p) {
    u32 a; asm("{ .reg .u64 t; cvta.to.shared.u64 t, %1; cvt.u32.u64 %0, t; }" : "=r"(a) : "l"(p));
    return a;
}
__device__ __forceinline__ void cpa16(u32 dst, const void* src, bool valid) {
    int sz = valid ? 16 : 0;
    asm volatile("cp.async.ca.shared.global [%0], [%1], 16, %2;"
                 :: "r"(dst), "l"(src), "r"(sz) : "memory");
}
#define CP_COMMIT() asm volatile("cp.async.commit_group;" ::: "memory")
#define CP_WAIT(n)  asm volatile("cp.async.wait_group %0;" :: "n"(n) : "memory")

__device__ __forceinline__ void mma_f16(float* c, u32 a0, u32 a1, u32 a2, u32 a3,
                                        u32 b0, u32 b1) {
    asm volatile("mma.sync.aligned.m16n8k16.row.col.f32.f16.f16.f32 "
                 "{%0,%1,%2,%3}, {%4,%5,%6,%7}, {%8,%9}, {%0,%1,%2,%3};"
                 : "+f"(c[0]), "+f"(c[1]), "+f"(c[2]), "+f"(c[3])
                 : "r"(a0), "r"(a1), "r"(a2), "r"(a3), "r"(b0), "r"(b1));
}
__device__ __forceinline__ void lds64(u32& r0, u32& r1, u32 addr) {
    asm volatile("ld.shared.v2.b32 {%0, %1}, [%2];" : "=r"(r0), "=r"(r1) : "r"(addr));
}
__device__ __forceinline__ u32 packh2(float a, float b) {
    __half2 h = __floats2half2_rn(a, b);
    return *(u32*)&h;
}

// ---------------- prep kernels ----------------
__global__ void decode_idx(const int* __restrict__ yr, const int* __restrict__ ar) {
    __shared__ int is64;
    int t = threadIdx.x;
    if (t == 0) {
        int acc = 0;
        for (int i = 1; i < NB; i += 2) acc |= yr[i];
        is64 = (acc == 0) ? 1 : 0;
    }
    __syncthreads();
    if (t < NB) {
        int st = is64 ? 2 : 1;
        g_y[t]   = yr[t * st];
        g_arc[t] = ar[t * st];
    }
    __syncthreads();
    if (t == 0) {
        int n = 0;
        for (int br = 3; br >= 0; br--)
            for (int i = 0; i < NB; i++)
                if (g_arc[i] == br) g_order[n++] = i;
    }
}

// Pack weights into fragment-lane order.
__global__ void transform_w(const float* __restrict__ w0, const float* __restrict__ w1,
                            const float* __restrict__ w2, const float* __restrict__ w3) {
    int br = blockIdx.y;
    const float* w = (br == 0) ? w0 : (br == 1) ? w1 : (br == 2) ? w2 : w3;
    int k = 2 * br + 1, kk = k * k;
    int off = c_woffw[br];
    int total = kk * 32768;
    for (int i = blockIdx.x * 256 + threadIdx.x; i < total; i += gridDim.x * 256) {
        int rs   = i >> 15;
        int rem  = i & 32767;
        int chunk = rem >> 12;
        int rem3 = rem & 4095;
        int tile = rem3 >> 8;
        int rem4 = rem3 & 255;
        int ks   = rem4 >> 7;
        int rem5 = rem4 & 127;
        int lane = rem5 >> 2, q = rem5 & 3;
        int g = lane >> 2, t = lane & 3;
        int row = tile * 16 + g + ((q & 1) << 3);
        int cl  = t + ((q >> 1) << 2);
        int ch  = chunk * 32 + ks * 16 + cl * 2;
        int base = (row * 256 + ch) * kk + rs;
        g_wf[off + i] = packh2(w[base], w[base + kk]);
    }
}

// Repack x channel-innermost with cp interleave, via smem transpose.
__global__ void transform_x(const float* __restrict__ x) {
    __shared__ __half sm[32][132];
    int b  = blockIdx.x >> 3;
    int pb = blockIdx.x & 7;
    int tid = threadIdx.x;
    for (int chunk = 0; chunk < 8; chunk++) {
        __syncthreads();
        for (int j = tid; j < 32 * 128; j += 256) {
            int c = j >> 7, p = j & 127;
            sm[c][p] = __float2half_rn(
                x[(((size_t)b * 256 + chunk * 32 + c) << 10) + pb * 128 + p]);
        }
        __syncthreads();
        for (int j = tid; j < 128 * 16; j += 256) {
            int p = j >> 4, wd = j & 15;
            int ks = wd >> 3, s = wd & 7;
            int cl = (s >> 1) + ((s & 1) << 2);
            int ch = ks * 16 + cl * 2;
            u32 val = packh2(__half2float(sm[ch][p]), __half2float(sm[ch + 1][p]));
            g_xb[((size_t)b << 17) + (size_t)(pb * 128 + p) * 128 + chunk * 16 + wd] = val;
        }
    }
}

// ---------------- main kernel ----------------
// CTA: (b, oct, pband). 256 thr = 8 warps (2m x 4n), warp tile 64oc x 64pix.
// A: fragment-packed LDG.128, register double-buffered (prefetch next rs).
// B smem: [ks2][R][40 cols][8 words], pixel stride 8 words (conflict-free LDS.64).
#define SMEM_BYTES (2 * 640 * 14 * 4)   // 2 buffers x 640*R_max words

__global__ void __launch_bounds__(256, 1)
conv_mma(const float* __restrict__ e0_, const float* __restrict__ e1_,
         const float* __restrict__ e2_, const float* __restrict__ e3_,
         float* __restrict__ out)
{
    extern __shared__ u32 smem[];
    const u32 sb = smem_u32(smem);

    const int tid  = threadIdx.x;
    const int wid  = tid >> 5, lane = tid & 31;
    const int g    = lane >> 2, t = lane & 3;
    const int wm   = wid >> 2;
    const int wn   = wid & 3;

    const int b     = g_order[blockIdx.x >> 3];
    const int oct   = (blockIdx.x >> 2) & 1;
    const int pband = blockIdx.x & 3;

    const int br = g_arc[b];
    const int k  = 2 * br + 1, pk = br, kk = k * k;
    const int R  = 7 + k;
    const int XW = 640 * R;                        // words per X buffer
    const float* eptr = (br == 0) ? e0_ : (br == 1) ? e1_ : (br == 2) ? e2_ : e3_;
    const int woffw = c_woffw[br];

    const u32 uX[2] = { sb, sb + (u32)XW * 4 };

    // per-nt pixel word offset within a (ks, shift) view, incl. fragment 2t
    int pixw[8];
    #pragma unroll
    for (int nt = 0; nt < 8; nt++) {
        int p = wn * 64 + nt * 8 + g;
        pixw[nt] = ((p >> 5) * 40 + (p & 31)) * 8 + 2 * t;
    }

    float acc[4][8][4];
    #pragma unroll
    for (int mt = 0; mt < 4; mt++)
        #pragma unroll
        for (int nt = 0; nt < 8; nt++)
            #pragma unroll
            for (int q = 0; q < 4; q++)
                acc[mt][nt][q] = 0.0f;

    const int h0   = pband * 8 - pk;
    const int NCP  = 160 * R;
    const int T80R = 80 * R;
    const u32* xb_img = g_xb + ((size_t)b << 17);

    #define ISSUE_X(chunk_, ub_) do { \
        _Pragma("unroll 1") \
        for (int id = tid; id < NCP; id += 256) { \
            int ks  = (id >= T80R); \
            int rem = id - ks * T80R; \
            int row = rem / 80; \
            int q_  = rem - row * 80; \
            int col = q_ >> 1, hh = q_ & 1; \
            int hr  = h0 + row, ic = col - 4; \
            bool valid = ((unsigned)hr < HW) && ((unsigned)ic < HW); \
            int pix = valid ? (hr * 32 + ic) : 0; \
            const u32* src = xb_img + (size_t)pix * 128 + (chunk_) * 16 + ks * 8 + hh * 4; \
            u32 dst = (ub_) + (u32)(ks * R * 320 + (row * 40 + col) * 8 + hh * 4) * 4; \
            cpa16(dst, src, valid); \
        } \
    } while (0)

    // A fragment load: buffer <- step rs of current chunk (tile=64u4, ks=32u4)
    #define LOADA(A_, rs_) do { \
        const uint4* ap_ = wchunk + (size_t)(rs_) * 8192; \
        _Pragma("unroll") \
        for (int j = 0; j < 8; j++) (A_)[j] = ap_[j * 32]; \
    } while (0)

    #define COMPUTE(A_) do { \
        const int shiftw = (r * 40 + s - pk + 4) * 8; \
        _Pragma("unroll") \
        for (int ks = 0; ks < 2; ks++) { \
            u32 rb[8][2]; \
            const u32 bka = xbuf + (u32)(ks * R * 320 + shiftw) * 4; \
            _Pragma("unroll") \
            for (int nt = 0; nt < 8; nt++) \
                lds64(rb[nt][0], rb[nt][1], bka + (u32)pixw[nt] * 4); \
            _Pragma("unroll") \
            for (int mt = 0; mt < 4; mt++) { \
                const uint4 av = (A_)[mt * 2 + ks]; \
                _Pragma("unroll") \
                for (int nt = 0; nt < 8; nt++) \
                    mma_f16(acc[mt][nt], av.x, av.y, av.z, av.w, \
                            rb[nt][0], rb[nt][1]); \
            } \
        } \
        if (++s == k) { s = 0; ++r; } \
    } while (0)

    ISSUE_X(0, uX[0]);
    CP_COMMIT();

    #pragma unroll 1
    for (int chunk = 0; chunk < 8; chunk++) {
        CP_WAIT(0);
        __syncthreads();
        if (chunk < 7) {
            ISSUE_X(chunk + 1, uX[(chunk + 1) & 1]);
            CP_COMMIT();
        }
        const u32 xbuf = uX[chunk & 1];
        const uint4* wchunk = (const uint4*)(g_wf + woffw
            + (size_t)((chunk * 16 + oct * 8 + wm * 4) * 256) + (lane << 2));

        int r = 0, s = 0;
        uint4 AE[8], AO[8];
        LOADA(AE, 0);
        // paired even/odd steps with one-step A prefetch; kk odd -> even tail
        #pragma unroll 1
        for (int rs = 0; rs + 1 < kk; rs += 2) {
            LOADA(AO, rs + 1);
            COMPUTE(AE);
            if (rs + 2 < kk) LOADA(AE, rs + 2);
            COMPUTE(AO);
        }
        COMPUTE(AE);
    }

    // ---- epilogue: += class embedding, store ----
    const int yb = g_y[b];
    const int ocg = oct * 128 + wm * 64;
    #pragma unroll
    for (int mt = 0; mt < 4; mt++) {
        int oc_lo = ocg + mt * 16 + g;
        int oc_hi = oc_lo + 8;
        float ev_lo = eptr[yb * OUT_C + oc_lo];
        float ev_hi = eptr[yb * OUT_C + oc_hi];
        float* base_lo = out + (size_t)(b * OUT_C + oc_lo) * NPIX + pband * 256;
        float* base_hi = out + (size_t)(b * OUT_C + oc_hi) * NPIX + pband * 256;
        #pragma unroll
        for (int nt = 0; nt < 8; nt++) {
            int p = wn * 64 + nt * 8 + 2 * t;
            float2 vlo = make_float2(acc[mt][nt][0] + ev_lo, acc[mt][nt][1] + ev_lo);
            float2 vhi = make_float2(acc[mt][nt][2] + ev_hi, acc[mt][nt][3] + ev_hi);
            *(float2*)(base_lo + p) = vlo;
            *(float2*)(base_hi + p) = vhi;
        }
    }
}

// ---------------- launcher ----------------
extern "C" void kernel_launch(void* const* d_in, const int* in_sizes, int n_in,
                              void* d_out, int out_size) {
    const float* x = nullptr;
    const int *yr = nullptr, *ar = nullptr;
    const float* w[4] = {nullptr, nullptr, nullptr, nullptr};
    const float* e[4] = {nullptr, nullptr, nullptr, nullptr};
    int ne = 0, n64 = 0;

    for (int i = 0; i < n_in; i++) {
        int sz = in_sizes[i];
        const void* p = d_in[i];
        if      (sz == 16777216) x = (const float*)p;
        else if (sz == 64)       { if (n64++ == 0) yr = (const int*)p; else ar = (const int*)p; }
        else if (sz == 65536)    w[0] = (const float*)p;
        else if (sz == 589824)   w[1] = (const float*)p;
        else if (sz == 1638400)  w[2] = (const float*)p;
        else if (sz == 3211264)  w[3] = (const float*)p;
        else if (sz == 256000)   { if (ne < 4) e[ne++] = (const float*)p; }
    }

    cudaFuncSetAttribute(conv_mma, cudaFuncAttributeMaxDynamicSharedMemorySize, SMEM_BYTES);

    decode_idx<<<1, 64>>>(yr, ar);
    transform_w<<<dim3(512, 4), 256>>>(w[0], w[1], w[2], w[3]);
    transform_x<<<512, 256>>>(x);
    conv_mma<<<512, 256, SMEM_BYTES>>>(e[0], e[1], e[2], e[3], (float*)d_out);
}

// round 13
// speedup vs baseline: 1.0475x; 1.0475x over previous
#include <cuda_runtime.h>
#include <cuda_fp16.h>
#include <cstdint>

typedef uint32_t u32;

#define IN_C  256
#define OUT_C 256
#define HW    32
#define NB    64
#define NPIX  1024

__device__ int g_y[NB];
__device__ int g_arc[NB];
__device__ int g_order[NB];
// fragment-packed fp16 weights: [br][rs][chunk8][tile16][ks2][lane32][4 words]
__device__ u32 g_wf[2752512];
// repacked fp16 x: [b][pix][chunk8][ks2][slot8] words; slot order cp(0,4,1,5,2,6,3,7)
__device__ u32 g_xb[8388608];

__constant__ int c_woffw[4] = {0, 32768, 327680, 1146880};

// ---------------- helpers ----------------
__device__ __forceinline__ u32 smem_u32(const void* p) {
    u32 a; asm("{ .reg .u64 t; cvta.to.shared.u64 t, %1; cvt.u32.u64 %0, t; }" : "=r"(a) : "l"(p));
    return a;
}
__device__ __forceinline__ void cpa16(u32 dst, const void* src, bool valid) {
    int sz = valid ? 16 : 0;
    asm volatile("cp.async.ca.shared.global [%0], [%1], 16, %2;"
                 :: "r"(dst), "l"(src), "r"(sz) : "memory");
}
#define CP_COMMIT() asm volatile("cp.async.commit_group;" ::: "memory")
#define CP_WAIT(n)  asm volatile("cp.async.wait_group %0;" :: "n"(n) : "memory")

__device__ __forceinline__ void mma_f16(float* c, u32 a0, u32 a1, u32 a2, u32 a3,
                                        u32 b0, u32 b1) {
    asm volatile("mma.sync.aligned.m16n8k16.row.col.f32.f16.f16.f32 "
                 "{%0,%1,%2,%3}, {%4,%5,%6,%7}, {%8,%9}, {%0,%1,%2,%3};"
                 : "+f"(c[0]), "+f"(c[1]), "+f"(c[2]), "+f"(c[3])
                 : "r"(a0), "r"(a1), "r"(a2), "r"(a3), "r"(b0), "r"(b1));
}
__device__ __forceinline__ void lds64(u32& r0, u32& r1, u32 addr) {
    asm volatile("ld.shared.v2.b32 {%0, %1}, [%2];" : "=r"(r0), "=r"(r1) : "r"(addr));
}
__device__ __forceinline__ u32 packh2(float a, float b) {
    __half2 h = __floats2half2_rn(a, b);
    return *(u32*)&h;
}

// ---------------- prep kernels ----------------
// transform_w also performs index decode in block (0,0).
__global__ void transform_w(const int* __restrict__ yr, const int* __restrict__ ar,
                            const float* __restrict__ w0, const float* __restrict__ w1,
                            const float* __restrict__ w2, const float* __restrict__ w3) {
    if (blockIdx.x == 0 && blockIdx.y == 0) {
        __shared__ int is64;
        int t = threadIdx.x;
        if (t == 0) {
            int acc = 0;
            for (int i = 1; i < NB; i += 2) acc |= yr[i];
            is64 = (acc == 0) ? 1 : 0;
        }
        __syncthreads();
        if (t < NB) {
            int st = is64 ? 2 : 1;
            g_y[t]   = yr[t * st];
            g_arc[t] = ar[t * st];
        }
        __syncthreads();
        if (t == 0) {
            int n = 0;
            for (int br = 3; br >= 0; br--)
                for (int i = 0; i < NB; i++)
                    if (g_arc[i] == br) g_order[n++] = i;
        }
    }
    int br = blockIdx.y;
    const float* w = (br == 0) ? w0 : (br == 1) ? w1 : (br == 2) ? w2 : w3;
    int k = 2 * br + 1, kk = k * k;
    int off = c_woffw[br];
    int total = kk * 32768;
    for (int i = blockIdx.x * 256 + threadIdx.x; i < total; i += gridDim.x * 256) {
        int rs   = i >> 15;
        int rem  = i & 32767;
        int chunk = rem >> 12;
        int rem3 = rem & 4095;
        int tile = rem3 >> 8;
        int rem4 = rem3 & 255;
        int ks   = rem4 >> 7;
        int rem5 = rem4 & 127;
        int lane = rem5 >> 2, q = rem5 & 3;
        int g = lane >> 2, t = lane & 3;
        int row = tile * 16 + g + ((q & 1) << 3);
        int cl  = t + ((q >> 1) << 2);
        int ch  = chunk * 32 + ks * 16 + cl * 2;
        int base = (row * 256 + ch) * kk + rs;
        g_wf[off + i] = packh2(w[base], w[base + kk]);
    }
}

// Repack x channel-innermost with cp interleave: one block per (b, pb, chunk).
__global__ void transform_x(const float* __restrict__ x) {
    __shared__ __half sm[32][132];
    int bid   = blockIdx.x;
    int chunk = bid & 7;
    int pb    = (bid >> 3) & 7;
    int b     = bid >> 6;
    int tid   = threadIdx.x;
    for (int j = tid; j < 32 * 128; j += 256) {
        int c = j >> 7, p = j & 127;
        sm[c][p] = __float2half_rn(
            x[(((size_t)b * 256 + chunk * 32 + c) << 10) + pb * 128 + p]);
    }
    __syncthreads();
    for (int j = tid; j < 128 * 16; j += 256) {
        int p = j >> 4, wd = j & 15;
        int ks = wd >> 3, s = wd & 7;
        int cl = (s >> 1) + ((s & 1) << 2);
        int ch = ks * 16 + cl * 2;
        u32 val = packh2(__half2float(sm[ch][p]), __half2float(sm[ch + 1][p]));
        g_xb[((size_t)b << 17) + (size_t)(pb * 128 + p) * 128 + chunk * 16 + wd] = val;
    }
}

// ---------------- main kernel ----------------
// CTA: (b, oct, pband). 256 thr = 8 warps (2m x 4n), warp tile 64oc x 64pix.
// A: fragment-packed LDG.128, half-step pipelined via two static 4-frag buffers.
// B smem: [ks2][R][40 cols][8 words], pixel stride 8 words (conflict-free LDS.64).
#define SMEM_BYTES (2 * 640 * 14 * 4)   // 2 buffers x 640*R_max words

__global__ void __launch_bounds__(256, 1)
conv_mma(const float* __restrict__ e0_, const float* __restrict__ e1_,
         const float* __restrict__ e2_, const float* __restrict__ e3_,
         float* __restrict__ out)
{
    extern __shared__ u32 smem[];
    const u32 sb = smem_u32(smem);

    const int tid  = threadIdx.x;
    const int wid  = tid >> 5, lane = tid & 31;
    const int g    = lane >> 2, t = lane & 3;
    const int wm   = wid >> 2;
    const int wn   = wid & 3;

    const int b     = g_order[blockIdx.x >> 3];
    const int oct   = (blockIdx.x >> 2) & 1;
    const int pband = blockIdx.x & 3;

    const int br = g_arc[b];
    const int k  = 2 * br + 1, pk = br, kk = k * k;
    const int R  = 7 + k;
    const int XW = 640 * R;                        // words per X buffer
    const float* eptr = (br == 0) ? e0_ : (br == 1) ? e1_ : (br == 2) ? e2_ : e3_;
    const int woffw = c_woffw[br];

    const u32 uX[2] = { sb, sb + (u32)XW * 4 };

    int pixw[8];
    #pragma unroll
    for (int nt = 0; nt < 8; nt++) {
        int p = wn * 64 + nt * 8 + g;
        pixw[nt] = ((p >> 5) * 40 + (p & 31)) * 8 + 2 * t;
    }

    float acc[4][8][4];
    #pragma unroll
    for (int mt = 0; mt < 4; mt++)
        #pragma unroll
        for (int nt = 0; nt < 8; nt++)
            #pragma unroll
            for (int q = 0; q < 4; q++)
                acc[mt][nt][q] = 0.0f;

    const int h0   = pband * 8 - pk;
    const int NCP  = 160 * R;
    const int T80R = 80 * R;
    const u32* xb_img = g_xb + ((size_t)b << 17);

    #define ISSUE_X(chunk_, ub_) do { \
        _Pragma("unroll 1") \
        for (int id = tid; id < NCP; id += 256) { \
            int ks  = (id >= T80R); \
            int rem = id - ks * T80R; \
            int row = rem / 80; \
            int q_  = rem - row * 80; \
            int col = q_ >> 1, hh = q_ & 1; \
            int hr  = h0 + row, ic = col - 4; \
            bool valid = ((unsigned)hr < HW) && ((unsigned)ic < HW); \
            int pix = valid ? (hr * 32 + ic) : 0; \
            const u32* src = xb_img + (size_t)pix * 128 + (chunk_) * 16 + ks * 8 + hh * 4; \
            u32 dst = (ub_) + (u32)(ks * R * 320 + (row * 40 + col) * 8 + hh * 4) * 4; \
            cpa16(dst, src, valid); \
        } \
    } while (0)

    // load one ks-half of A fragments (4x LDG.128); tile=64u4, ks=32u4
    #define LOADH(A_, rs_, ks_) do { \
        const uint4* ap_ = wchunk + (size_t)(rs_) * 8192 + (ks_) * 32; \
        _Pragma("unroll") \
        for (int mt = 0; mt < 4; mt++) (A_)[mt] = ap_[mt * 64]; \
    } while (0)

    // compute one ks-half: 8 LDS.64 + 32 HMMA
    #define COMPUTE_HALF(A_, ks_) do { \
        const int shiftw = (r * 40 + s - pk + 4) * 8; \
        u32 rb[8][2]; \
        const u32 bka = xbuf + (u32)((ks_) * R * 320 + shiftw) * 4; \
        _Pragma("unroll") \
        for (int nt = 0; nt < 8; nt++) \
            lds64(rb[nt][0], rb[nt][1], bka + (u32)pixw[nt] * 4); \
        _Pragma("unroll") \
        for (int mt = 0; mt < 4; mt++) { \
            const uint4 av = (A_)[mt]; \
            _Pragma("unroll") \
            for (int nt = 0; nt < 8; nt++) \
                mma_f16(acc[mt][nt], av.x, av.y, av.z, av.w, \
                        rb[nt][0], rb[nt][1]); \
        } \
    } while (0)

    ISSUE_X(0, uX[0]);
    CP_COMMIT();

    #pragma unroll 1
    for (int chunk = 0; chunk < 8; chunk++) {
        const u32 xbuf = uX[chunk & 1];
        const uint4* wchunk = (const uint4*)(g_wf + woffw
            + (size_t)((chunk * 16 + oct * 8 + wm * 4) * 256) + (lane << 2));

        uint4 HA[4], HB[4];
        LOADH(HA, 0, 0);            // overlaps the X wait below
        CP_WAIT(0);
        __syncthreads();
        if (chunk < 7) {
            ISSUE_X(chunk + 1, uX[(chunk + 1) & 1]);
            CP_COMMIT();
        }

        int r = 0, s = 0;
        #pragma unroll 1
        for (int rs = 0; rs < kk; rs++) {
            LOADH(HB, rs, 1);       // ks=1 half, leads its use by one half-step
            COMPUTE_HALF(HA, 0);
            if (rs + 1 < kk) LOADH(HA, rs + 1, 0);
            COMPUTE_HALF(HB, 1);
            if (++s == k) { s = 0; ++r; }
        }
    }

    // ---- epilogue: += class embedding, store ----
    const int yb = g_y[b];
    const int ocg = oct * 128 + wm * 64;
    #pragma unroll
    for (int mt = 0; mt < 4; mt++) {
        int oc_lo = ocg + mt * 16 + g;
        int oc_hi = oc_lo + 8;
        float ev_lo = eptr[yb * OUT_C + oc_lo];
        float ev_hi = eptr[yb * OUT_C + oc_hi];
        float* base_lo = out + (size_t)(b * OUT_C + oc_lo) * NPIX + pband * 256;
        float* base_hi = out + (size_t)(b * OUT_C + oc_hi) * NPIX + pband * 256;
        #pragma unroll
        for (int nt = 0; nt < 8; nt++) {
            int p = wn * 64 + nt * 8 + 2 * t;
            float2 vlo = make_float2(acc[mt][nt][0] + ev_lo, acc[mt][nt][1] + ev_lo);
            float2 vhi = make_float2(acc[mt][nt][2] + ev_hi, acc[mt][nt][3] + ev_hi);
            *(float2*)(base_lo + p) = vlo;
            *(float2*)(base_hi + p) = vhi;
        }
    }
}

// ---------------- launcher ----------------
extern "C" void kernel_launch(void* const* d_in, const int* in_sizes, int n_in,
                              void* d_out, int out_size) {
    const float* x = nullptr;
    const int *yr = nullptr, *ar = nullptr;
    const float* w[4] = {nullptr, nullptr, nullptr, nullptr};
    const float* e[4] = {nullptr, nullptr, nullptr, nullptr};
    int ne = 0, n64 = 0;

    for (int i = 0; i < n_in; i++) {
        int sz = in_sizes[i];
        const void* p = d_in[i];
        if      (sz == 16777216) x = (const float*)p;
        else if (sz == 64)       { if (n64++ == 0) yr = (const int*)p; else ar = (const int*)p; }
        else if (sz == 65536)    w[0] = (const float*)p;
        else if (sz == 589824)   w[1] = (const float*)p;
        else if (sz == 1638400)  w[2] = (const float*)p;
        else if (sz == 3211264)  w[3] = (const float*)p;
        else if (sz == 256000)   { if (ne < 4) e[ne++] = (const float*)p; }
    }

    cudaFuncSetAttribute(conv_mma, cudaFuncAttributeMaxDynamicSharedMemorySize, SMEM_BYTES);

    transform_w<<<dim3(512, 4), 256>>>(yr, ar, w[0], w[1], w[2], w[3]);
    transform_x<<<4096, 256>>>(x);
    conv_mma<<<512, 256, SMEM_BYTES>>>(e[0], e[1], e[2], e[3], (float*)d_out);
}

// round 14
// speedup vs baseline: 1.3445x; 1.2836x over previous
#include <cuda_runtime.h>
#include <cuda_fp16.h>
#include <cstdint>

typedef uint32_t u32;

#define IN_C  256
#define OUT_C 256
#define HW    32
#define NB    64
#define NPIX  1024

__device__ int g_y[NB];
__device__ int g_arc[NB];
__device__ int g_order[NB];
// fragment-packed fp16 weights: [br][rs][chunk8][tile16][ks2][lane32][4 words]
__device__ u32 g_wf[2752512];
// repacked fp16 x: [b][pix][chunk8][ks2][slot8] words; slot order cp(0,4,1,5,2,6,3,7)
__device__ u32 g_xb[8388608];

__constant__ int c_woffw[4] = {0, 32768, 327680, 1146880};

// ---------------- helpers ----------------
__device__ __forceinline__ u32 smem_u32(const void* p) {
    u32 a; asm("{ .reg .u64 t; cvta.to.shared.u64 t, %1; cvt.u32.u64 %0, t; }" : "=r"(a) : "l"(p));
    return a;
}
__device__ __forceinline__ void cpa16(u32 dst, const void* src, bool valid) {
    int sz = valid ? 16 : 0;
    asm volatile("cp.async.ca.shared.global [%0], [%1], 16, %2;"
                 :: "r"(dst), "l"(src), "r"(sz) : "memory");
}
#define CP_COMMIT() asm volatile("cp.async.commit_group;" ::: "memory")
#define CP_WAIT(n)  asm volatile("cp.async.wait_group %0;" :: "n"(n) : "memory")

__device__ __forceinline__ void mma_f16(float* c, u32 a0, u32 a1, u32 a2, u32 a3,
                                        u32 b0, u32 b1) {
    asm volatile("mma.sync.aligned.m16n8k16.row.col.f32.f16.f16.f32 "
                 "{%0,%1,%2,%3}, {%4,%5,%6,%7}, {%8,%9}, {%0,%1,%2,%3};"
                 : "+f"(c[0]), "+f"(c[1]), "+f"(c[2]), "+f"(c[3])
                 : "r"(a0), "r"(a1), "r"(a2), "r"(a3), "r"(b0), "r"(b1));
}
__device__ __forceinline__ void lds64(u32& r0, u32& r1, u32 addr) {
    asm volatile("ld.shared.v2.b32 {%0, %1}, [%2];" : "=r"(r0), "=r"(r1) : "r"(addr));
}
__device__ __forceinline__ u32 packh2(float a, float b) {
    __half2 h = __floats2half2_rn(a, b);
    return *(u32*)&h;
}

// ---------------- prep kernels ----------------
// transform_w also performs index decode in block (0,0).
__global__ void transform_w(const int* __restrict__ yr, const int* __restrict__ ar,
                            const float* __restrict__ w0, const float* __restrict__ w1,
                            const float* __restrict__ w2, const float* __restrict__ w3) {
    if (blockIdx.x == 0 && blockIdx.y == 0) {
        __shared__ int is64;
        int t = threadIdx.x;
        if (t == 0) {
            int acc = 0;
            for (int i = 1; i < NB; i += 2) acc |= yr[i];
            is64 = (acc == 0) ? 1 : 0;
        }
        __syncthreads();
        if (t < NB) {
            int st = is64 ? 2 : 1;
            g_y[t]   = yr[t * st];
            g_arc[t] = ar[t * st];
        }
        __syncthreads();
        if (t == 0) {
            int n = 0;
            for (int br = 3; br >= 0; br--)
                for (int i = 0; i < NB; i++)
                    if (g_arc[i] == br) g_order[n++] = i;
        }
    }
    int br = blockIdx.y;
    const float* w = (br == 0) ? w0 : (br == 1) ? w1 : (br == 2) ? w2 : w3;
    int k = 2 * br + 1, kk = k * k;
    int off = c_woffw[br];
    int total = kk * 32768;
    for (int i = blockIdx.x * 256 + threadIdx.x; i < total; i += gridDim.x * 256) {
        int rs   = i >> 15;
        int rem  = i & 32767;
        int chunk = rem >> 12;
        int rem3 = rem & 4095;
        int tile = rem3 >> 8;
        int rem4 = rem3 & 255;
        int ks   = rem4 >> 7;
        int rem5 = rem4 & 127;
        int lane = rem5 >> 2, q = rem5 & 3;
        int g = lane >> 2, t = lane & 3;
        int row = tile * 16 + g + ((q & 1) << 3);
        int cl  = t + ((q >> 1) << 2);
        int ch  = chunk * 32 + ks * 16 + cl * 2;
        int base = (row * 256 + ch) * kk + rs;
        g_wf[off + i] = packh2(w[base], w[base + kk]);
    }
}

// Repack x channel-innermost with cp interleave: one block per (b, pb, chunk).
__global__ void transform_x(const float* __restrict__ x) {
    __shared__ __half sm[32][132];
    int bid   = blockIdx.x;
    int chunk = bid & 7;
    int pb    = (bid >> 3) & 7;
    int b     = bid >> 6;
    int tid   = threadIdx.x;
    for (int j = tid; j < 32 * 128; j += 256) {
        int c = j >> 7, p = j & 127;
        sm[c][p] = __float2half_rn(
            x[(((size_t)b * 256 + chunk * 32 + c) << 10) + pb * 128 + p]);
    }
    __syncthreads();
    for (int j = tid; j < 128 * 16; j += 256) {
        int p = j >> 4, wd = j & 15;
        int ks = wd >> 3, s = wd & 7;
        int cl = (s >> 1) + ((s & 1) << 2);
        int ch = ks * 16 + cl * 2;
        u32 val = packh2(__half2float(sm[ch][p]), __half2float(sm[ch + 1][p]));
        g_xb[((size_t)b << 17) + (size_t)(pb * 128 + p) * 128 + chunk * 16 + wd] = val;
    }
}

// ---------------- main kernel (round-11 structure) ----------------
// CTA: (b, oct, pband). 256 thr = 8 warps (2m x 4n), warp tile 64oc x 64pix.
// A: fragment-packed LDG.128 direct to registers (8 per rs-step, MLP=8).
// B smem: [ks2][R][40 cols][8 words], pixel stride 8 words (conflict-free LDS.64).
#define SMEM_BYTES (2 * 640 * 14 * 4)   // 2 buffers x 640*R_max words

__global__ void __launch_bounds__(256, 1)
conv_mma(const float* __restrict__ e0_, const float* __restrict__ e1_,
         const float* __restrict__ e2_, const float* __restrict__ e3_,
         float* __restrict__ out)
{
    extern __shared__ u32 smem[];
    const u32 sb = smem_u32(smem);

    const int tid  = threadIdx.x;
    const int wid  = tid >> 5, lane = tid & 31;
    const int g    = lane >> 2, t = lane & 3;
    const int wm   = wid >> 2;
    const int wn   = wid & 3;

    const int b     = g_order[blockIdx.x >> 3];
    const int oct   = (blockIdx.x >> 2) & 1;
    const int pband = blockIdx.x & 3;

    const int br = g_arc[b];
    const int k  = 2 * br + 1, pk = br, kk = k * k;
    const int R  = 7 + k;
    const int XW = 640 * R;                        // words per X buffer
    const float* eptr = (br == 0) ? e0_ : (br == 1) ? e1_ : (br == 2) ? e2_ : e3_;
    const int woffw = c_woffw[br];

    const u32 uX[2] = { sb, sb + (u32)XW * 4 };

    // per-nt pixel word offset within a (ks, shift) view, incl. fragment 2t
    int pixw[8];
    #pragma unroll
    for (int nt = 0; nt < 8; nt++) {
        int p = wn * 64 + nt * 8 + g;
        pixw[nt] = ((p >> 5) * 40 + (p & 31)) * 8 + 2 * t;
    }

    float acc[4][8][4];
    #pragma unroll
    for (int mt = 0; mt < 4; mt++)
        #pragma unroll
        for (int nt = 0; nt < 8; nt++)
            #pragma unroll
            for (int q = 0; q < 4; q++)
                acc[mt][nt][q] = 0.0f;

    const int h0   = pband * 8 - pk;
    const int NCP  = 160 * R;
    const int T80R = 80 * R;
    const u32* xb_img = g_xb + ((size_t)b << 17);

    #define ISSUE_X(chunk_, ub_) do { \
        _Pragma("unroll 1") \
        for (int id = tid; id < NCP; id += 256) { \
            int ks  = (id >= T80R); \
            int rem = id - ks * T80R; \
            int row = rem / 80; \
            int q_  = rem - row * 80; \
            int col = q_ >> 1, hh = q_ & 1; \
            int hr  = h0 + row, ic = col - 4; \
            bool valid = ((unsigned)hr < HW) && ((unsigned)ic < HW); \
            int pix = valid ? (hr * 32 + ic) : 0; \
            const u32* src = xb_img + (size_t)pix * 128 + (chunk_) * 16 + ks * 8 + hh * 4; \
            u32 dst = (ub_) + (u32)(ks * R * 320 + (row * 40 + col) * 8 + hh * 4) * 4; \
            cpa16(dst, src, valid); \
        } \
    } while (0)

    ISSUE_X(0, uX[0]);
    CP_COMMIT();

    #pragma unroll 1
    for (int chunk = 0; chunk < 8; chunk++) {
        CP_WAIT(0);
        __syncthreads();
        if (chunk < 7) {
            ISSUE_X(chunk + 1, uX[(chunk + 1) & 1]);
            CP_COMMIT();
        }
        const u32 xbuf = uX[chunk & 1];
        // warp's A fragment base for this chunk: [rs][chunk][tile][ks][lane][4]
        const uint4* wchunk = (const uint4*)(g_wf + woffw
            + (size_t)((chunk * 16 + oct * 8 + wm * 4) * 256) + (lane << 2));

        int r = 0, s = 0;
        #pragma unroll 1
        for (int rs = 0; rs < kk; rs++) {
            // ---- A: 8 coalesced LDG.128 (L2-resident), MLP=8 ----
            // layout: tile stride = 64 uint4, ks stride = 32 uint4
            uint4 a[8];
            const uint4* ap = wchunk + (size_t)rs * 8192;
            #pragma unroll
            for (int j = 0; j < 8; j++)
                a[j] = ap[j * 32];                          // j = mt*2+ks

            const int shiftw = (r * 40 + s - pk + 4) * 8;
            #pragma unroll
            for (int ks = 0; ks < 2; ks++) {
                u32 rb[8][2];
                const u32 bka = xbuf + (u32)(ks * R * 320 + shiftw) * 4;
                #pragma unroll
                for (int nt = 0; nt < 8; nt++)
                    lds64(rb[nt][0], rb[nt][1], bka + (u32)pixw[nt] * 4);
                #pragma unroll
                for (int mt = 0; mt < 4; mt++) {
                    const uint4 av = a[mt * 2 + ks];
                    #pragma unroll
                    for (int nt = 0; nt < 8; nt++)
                        mma_f16(acc[mt][nt], av.x, av.y, av.z, av.w,
                                rb[nt][0], rb[nt][1]);
                }
            }
            if (++s == k) { s = 0; ++r; }
        }
    }

    // ---- epilogue: += class embedding, store ----
    const int yb = g_y[b];
    const int ocg = oct * 128 + wm * 64;
    #pragma unroll
    for (int mt = 0; mt < 4; mt++) {
        int oc_lo = ocg + mt * 16 + g;
        int oc_hi = oc_lo + 8;
        float ev_lo = eptr[yb * OUT_C + oc_lo];
        float ev_hi = eptr[yb * OUT_C + oc_hi];
        float* base_lo = out + (size_t)(b * OUT_C + oc_lo) * NPIX + pband * 256;
        float* base_hi = out + (size_t)(b * OUT_C + oc_hi) * NPIX + pband * 256;
        #pragma unroll
        for (int nt = 0; nt < 8; nt++) {
            int p = wn * 64 + nt * 8 + 2 * t;
            float2 vlo = make_float2(acc[mt][nt][0] + ev_lo, acc[mt][nt][1] + ev_lo);
            float2 vhi = make_float2(acc[mt][nt][2] + ev_hi, acc[mt][nt][3] + ev_hi);
            *(float2*)(base_lo + p) = vlo;
            *(float2*)(base_hi + p) = vhi;
        }
    }
}

// ---------------- launcher ----------------
extern "C" void kernel_launch(void* const* d_in, const int* in_sizes, int n_in,
                              void* d_out, int out_size) {
    const float* x = nullptr;
    const int *yr = nullptr, *ar = nullptr;
    const float* w[4] = {nullptr, nullptr, nullptr, nullptr};
    const float* e[4] = {nullptr, nullptr, nullptr, nullptr};
    int ne = 0, n64 = 0;

    for (int i = 0; i < n_in; i++) {
        int sz = in_sizes[i];
        const void* p = d_in[i];
        if      (sz == 16777216) x = (const float*)p;
        else if (sz == 64)       { if (n64++ == 0) yr = (const int*)p; else ar = (const int*)p; }
        else if (sz == 65536)    w[0] = (const float*)p;
        else if (sz == 589824)   w[1] = (const float*)p;
        else if (sz == 1638400)  w[2] = (const float*)p;
        else if (sz == 3211264)  w[3] = (const float*)p;
        else if (sz == 256000)   { if (ne < 4) e[ne++] = (const float*)p; }
    }

    cudaFuncSetAttribute(conv_mma, cudaFuncAttributeMaxDynamicSharedMemorySize, SMEM_BYTES);

    transform_w<<<dim3(512, 4), 256>>>(yr, ar, w[0], w[1], w[2], w[3]);
    transform_x<<<4096, 256>>>(x);
    conv_mma<<<512, 256, SMEM_BYTES>>>(e[0], e[1], e[2], e[3], (float*)d_out);
}

// round 16
// speedup vs baseline: 1.4866x; 1.1057x over previous
#include <cuda_runtime.h>
#include <cuda_fp16.h>
#include <cstdint>

typedef uint32_t u32;

#define IN_C  256
#define OUT_C 256
#define HW    32
#define NB    64
#define NPIX  1024

__device__ int g_y[NB];
__device__ int g_arc[NB];
__device__ int g_order[NB];
// fragment-packed fp16 weights: [br][rs][chunk8][tile16][ks2][lane32][4 words]
__device__ u32 g_wf[2752512];
// repacked fp16 x: [b][pix][chunk8][ks2][slot8] words; slot order cp(0,4,1,5,2,6,3,7)
__device__ u32 g_xb[8388608];

__constant__ int c_woffw[4] = {0, 32768, 327680, 1146880};

// ---------------- helpers ----------------
__device__ __forceinline__ u32 smem_u32(const void* p) {
    u32 a; asm("{ .reg .u64 t; cvta.to.shared.u64 t, %1; cvt.u32.u64 %0, t; }" : "=r"(a) : "l"(p));
    return a;
}
__device__ __forceinline__ void cpa16(u32 dst, const void* src, bool valid) {
    int sz = valid ? 16 : 0;
    asm volatile("cp.async.ca.shared.global [%0], [%1], 16, %2;"
                 :: "r"(dst), "l"(src), "r"(sz) : "memory");
}
#define CP_COMMIT() asm volatile("cp.async.commit_group;" ::: "memory")
#define CP_WAIT(n)  asm volatile("cp.async.wait_group %0;" :: "n"(n) : "memory")

__device__ __forceinline__ void mma_f16(float* c, u32 a0, u32 a1, u32 a2, u32 a3,
                                        u32 b0, u32 b1) {
    asm volatile("mma.sync.aligned.m16n8k16.row.col.f32.f16.f16.f32 "
                 "{%0,%1,%2,%3}, {%4,%5,%6,%7}, {%8,%9}, {%0,%1,%2,%3};"
                 : "+f"(c[0]), "+f"(c[1]), "+f"(c[2]), "+f"(c[3])
                 : "r"(a0), "r"(a1), "r"(a2), "r"(a3), "r"(b0), "r"(b1));
}
__device__ __forceinline__ void lds64(u32& r0, u32& r1, u32 addr) {
    asm volatile("ld.shared.v2.b32 {%0, %1}, [%2];" : "=r"(r0), "=r"(r1) : "r"(addr));
}
__device__ __forceinline__ u32 packh2(float a, float b) {
    __half2 h = __floats2half2_rn(a, b);
    return *(u32*)&h;
}

// ---------------- prep kernels ----------------
// transform_w also performs index decode in block (0,0).
__global__ void transform_w(const int* __restrict__ yr, const int* __restrict__ ar,
                            const float* __restrict__ w0, const float* __restrict__ w1,
                            const float* __restrict__ w2, const float* __restrict__ w3) {
    if (blockIdx.x == 0 && blockIdx.y == 0) {
        __shared__ int is64;
        int t = threadIdx.x;
        if (t == 0) {
            int acc = 0;
            for (int i = 1; i < NB; i += 2) acc |= yr[i];
            is64 = (acc == 0) ? 1 : 0;
        }
        __syncthreads();
        if (t < NB) {
            int st = is64 ? 2 : 1;
            g_y[t]   = yr[t * st];
            g_arc[t] = ar[t * st];
        }
        __syncthreads();
        if (t == 0) {
            int n = 0;
            for (int br = 3; br >= 0; br--)
                for (int i = 0; i < NB; i++)
                    if (g_arc[i] == br) g_order[n++] = i;
        }
    }
    int br = blockIdx.y;
    const float* w = (br == 0) ? w0 : (br == 1) ? w1 : (br == 2) ? w2 : w3;
    int k = 2 * br + 1, kk = k * k;
    int off = c_woffw[br];
    int total = kk * 32768;
    for (int i = blockIdx.x * 256 + threadIdx.x; i < total; i += gridDim.x * 256) {
        int rs   = i >> 15;
        int rem  = i & 32767;
        int chunk = rem >> 12;
        int rem3 = rem & 4095;
        int tile = rem3 >> 8;
        int rem4 = rem3 & 255;
        int ks   = rem4 >> 7;
        int rem5 = rem4 & 127;
        int lane = rem5 >> 2, q = rem5 & 3;
        int g = lane >> 2, t = lane & 3;
        int row = tile * 16 + g + ((q & 1) << 3);
        int cl  = t + ((q >> 1) << 2);
        int ch  = chunk * 32 + ks * 16 + cl * 2;
        int base = (row * 256 + ch) * kk + rs;
        g_wf[off + i] = packh2(w[base], w[base + kk]);
    }
}

// Repack x channel-innermost with cp interleave: one block per (b, pb, chunk).
__global__ void transform_x(const float* __restrict__ x) {
    __shared__ __half sm[32][132];
    int bid   = blockIdx.x;
    int chunk = bid & 7;
    int pb    = (bid >> 3) & 7;
    int b     = bid >> 6;
    int tid   = threadIdx.x;
    for (int j = tid; j < 32 * 128; j += 256) {
        int c = j >> 7, p = j & 127;
        sm[c][p] = __float2half_rn(
            x[(((size_t)b * 256 + chunk * 32 + c) << 10) + pb * 128 + p]);
    }
    __syncthreads();
    for (int j = tid; j < 128 * 16; j += 256) {
        int p = j >> 4, wd = j & 15;
        int ks = wd >> 3, s = wd & 7;
        int cl = (s >> 1) + ((s & 1) << 2);
        int ch = ks * 16 + cl * 2;
        u32 val = packh2(__half2float(sm[ch][p]), __half2float(sm[ch + 1][p]));
        g_xb[((size_t)b << 17) + (size_t)(pb * 128 + p) * 128 + chunk * 16 + wd] = val;
    }
}

// ---------------- main kernel ----------------
// CTA: (b, oct, pband8). 256 thr = 8 warps (4m x 2n), warp tile 32oc x 64pix.
// CTA tile 128oc x 128pix (4 image rows). 2 CTAs/SM.
// A: fragment-packed LDG.128 (4 per rs-step). B smem: [ks2][R][40][8w], R=3+k.
#define SMEM_BYTES (2 * 640 * 10 * 4)   // 2 buffers x 640*R_max words = 51200B

__global__ void __launch_bounds__(256, 2)
conv_mma(const float* __restrict__ e0_, const float* __restrict__ e1_,
         const float* __restrict__ e2_, const float* __restrict__ e3_,
         float* __restrict__ out)
{
    extern __shared__ u32 smem[];
    const u32 sb = smem_u32(smem);

    const int tid  = threadIdx.x;
    const int wid  = tid >> 5, lane = tid & 31;
    const int g    = lane >> 2, t = lane & 3;
    const int wm   = wid >> 1;           // 0..3
    const int wn   = wid & 1;            // 0..1

    const int b     = g_order[blockIdx.x >> 4];
    const int oct   = (blockIdx.x >> 3) & 1;
    const int pband = blockIdx.x & 7;    // 4-row band

    const int br = g_arc[b];
    const int k  = 2 * br + 1, pk = br, kk = k * k;
    const int R  = 3 + k;
    const int XW = 640 * R;              // words per X buffer
    const float* eptr = (br == 0) ? e0_ : (br == 1) ? e1_ : (br == 2) ? e2_ : e3_;
    const int woffw = c_woffw[br];

    const u32 uX[2] = { sb, sb + (u32)XW * 4 };

    int pixw[8];
    #pragma unroll
    for (int nt = 0; nt < 8; nt++) {
        int p = wn * 64 + nt * 8 + g;
        pixw[nt] = ((p >> 5) * 40 + (p & 31)) * 8 + 2 * t;
    }

    float acc[2][8][4];
    #pragma unroll
    for (int mt = 0; mt < 2; mt++)
        #pragma unroll
        for (int nt = 0; nt < 8; nt++)
            #pragma unroll
            for (int q = 0; q < 4; q++)
                acc[mt][nt][q] = 0.0f;

    const int h0   = pband * 4 - pk;
    const int NCP  = 160 * R;
    const int T80R = 80 * R;
    const u32* xb_img = g_xb + ((size_t)b << 17);

    #define ISSUE_X(chunk_, ub_) do { \
        _Pragma("unroll 1") \
        for (int id = tid; id < NCP; id += 256) { \
            int ks  = (id >= T80R); \
            int rem = id - ks * T80R; \
            int row = rem / 80; \
            int q_  = rem - row * 80; \
            int col = q_ >> 1, hh = q_ & 1; \
            int hr  = h0 + row, ic = col - 4; \
            bool valid = ((unsigned)hr < HW) && ((unsigned)ic < HW); \
            int pix = valid ? (hr * 32 + ic) : 0; \
            const u32* src = xb_img + (size_t)pix * 128 + (chunk_) * 16 + ks * 8 + hh * 4; \
            u32 dst = (ub_) + (u32)(ks * R * 320 + (row * 40 + col) * 8 + hh * 4) * 4; \
            cpa16(dst, src, valid); \
        } \
    } while (0)

    ISSUE_X(0, uX[0]);
    CP_COMMIT();

    #pragma unroll 1
    for (int chunk = 0; chunk < 8; chunk++) {
        CP_WAIT(0);
        __syncthreads();
        if (chunk < 7) {
            ISSUE_X(chunk + 1, uX[(chunk + 1) & 1]);
            CP_COMMIT();
        }
        const u32 xbuf = uX[chunk & 1];
        // warp's A fragment base: 2 m16-tiles; tile stride 64u4, ks stride 32u4
        const uint4* wchunk = (const uint4*)(g_wf + woffw
            + (size_t)((chunk * 16 + oct * 8 + wm * 2) * 256) + (lane << 2));

        int r = 0, s = 0;
        #pragma unroll 1
        for (int rs = 0; rs < kk; rs++) {
            uint4 a[4];
            const uint4* ap = wchunk + (size_t)rs * 8192;
            #pragma unroll
            for (int j = 0; j < 4; j++)
                a[j] = ap[j * 32];                 // j = mt*2+ks

            const int shiftw = (r * 40 + s - pk + 4) * 8;
            #pragma unroll
            for (int ks = 0; ks < 2; ks++) {
                u32 rb[8][2];
                const u32 bka = xbuf + (u32)(ks * R * 320 + shiftw) * 4;
                #pragma unroll
                for (int nt = 0; nt < 8; nt++)
                    lds64(rb[nt][0], rb[nt][1], bka + (u32)pixw[nt] * 4);
                #pragma unroll
                for (int mt = 0; mt < 2; mt++) {
                    const uint4 av = a[mt * 2 + ks];
                    #pragma unroll
                    for (int nt = 0; nt < 8; nt++)
                        mma_f16(acc[mt][nt], av.x, av.y, av.z, av.w,
                                rb[nt][0], rb[nt][1]);
                }
            }
            if (++s == k) { s = 0; ++r; }
        }
    }

    // ---- epilogue: += class embedding, store ----
    const int yb = g_y[b];
    const int ocg = oct * 128 + wm * 32;
    #pragma unroll
    for (int mt = 0; mt < 2; mt++) {
        int oc_lo = ocg + mt * 16 + g;
        int oc_hi = oc_lo + 8;
        float ev_lo = eptr[yb * OUT_C + oc_lo];
        float ev_hi = eptr[yb * OUT_C + oc_hi];
        float* base_lo = out + (size_t)(b * OUT_C + oc_lo) * NPIX + pband * 128;
        float* base_hi = out + (size_t)(b * OUT_C + oc_hi) * NPIX + pband * 128;
        #pragma unroll
        for (int nt = 0; nt < 8; nt++) {
            int p = wn * 64 + nt * 8 + 2 * t;
            float2 vlo = make_float2(acc[mt][nt][0] + ev_lo, acc[mt][nt][1] + ev_lo);
            float2 vhi = make_float2(acc[mt][nt][2] + ev_hi, acc[mt][nt][3] + ev_hi);
            *(float2*)(base_lo + p) = vlo;
            *(float2*)(base_hi + p) = vhi;
        }
    }
}

// ---------------- launcher ----------------
extern "C" void kernel_launch(void* const* d_in, const int* in_sizes, int n_in,
                              void* d_out, int out_size) {
    const float* x = nullptr;
    const int *yr = nullptr, *ar = nullptr;
    const float* w[4] = {nullptr, nullptr, nullptr, nullptr};
    const float* e[4] = {nullptr, nullptr, nullptr, nullptr};
    int ne = 0, n64 = 0;

    for (int i = 0; i < n_in; i++) {
        int sz = in_sizes[i];
        const void* p = d_in[i];
        if      (sz == 16777216) x = (const float*)p;
        else if (sz == 64)       { if (n64++ == 0) yr = (const int*)p; else ar = (const int*)p; }
        else if (sz == 65536)    w[0] = (const float*)p;
        else if (sz == 589824)   w[1] = (const float*)p;
        else if (sz == 1638400)  w[2] = (const float*)p;
        else if (sz == 3211264)  w[3] = (const float*)p;
        else if (sz == 256000)   { if (ne < 4) e[ne++] = (const float*)p; }
    }

    cudaFuncSetAttribute(conv_mma, cudaFuncAttributeMaxDynamicSharedMemorySize, SMEM_BYTES);

    transform_w<<<dim3(512, 4), 256>>>(yr, ar, w[0], w[1], w[2], w[3]);
    transform_x<<<4096, 256>>>(x);
    conv_mma<<<1024, 256, SMEM_BYTES>>>(e[0], e[1], e[2], e[3], (float*)d_out);
}

// round 17
// speedup vs baseline: 1.5858x; 1.0667x over previous
#include <cuda_runtime.h>
#include <cuda_fp16.h>
#include <cstdint>

typedef uint32_t u32;

#define IN_C  256
#define OUT_C 256
#define HW    32
#define NB    64
#define NPIX  1024

__device__ int g_y[NB];
__device__ int g_arc[NB];
__device__ int g_order[NB];
// fragment-packed fp16 weights: [br][rs][chunk8][tile16][ks2][lane32][4 words]
__device__ u32 g_wf[2752512];
// repacked fp16 x: [b][pix][chunk8][ks2][slot8] words; slot order cp(0,4,1,5,2,6,3,7)
__device__ u32 g_xb[8388608];

__constant__ int c_woffw[4] = {0, 32768, 327680, 1146880};

// ---------------- helpers ----------------
__device__ __forceinline__ u32 smem_u32(const void* p) {
    u32 a; asm("{ .reg .u64 t; cvta.to.shared.u64 t, %1; cvt.u32.u64 %0, t; }" : "=r"(a) : "l"(p));
    return a;
}
__device__ __forceinline__ void cpa16(u32 dst, const void* src, bool valid) {
    int sz = valid ? 16 : 0;
    asm volatile("cp.async.ca.shared.global [%0], [%1], 16, %2;"
                 :: "r"(dst), "l"(src), "r"(sz) : "memory");
}
#define CP_COMMIT() asm volatile("cp.async.commit_group;" ::: "memory")
#define CP_WAIT(n)  asm volatile("cp.async.wait_group %0;" :: "n"(n) : "memory")

__device__ __forceinline__ void mma_f16(float* c, u32 a0, u32 a1, u32 a2, u32 a3,
                                        u32 b0, u32 b1) {
    asm volatile("mma.sync.aligned.m16n8k16.row.col.f32.f16.f16.f32 "
                 "{%0,%1,%2,%3}, {%4,%5,%6,%7}, {%8,%9}, {%0,%1,%2,%3};"
                 : "+f"(c[0]), "+f"(c[1]), "+f"(c[2]), "+f"(c[3])
                 : "r"(a0), "r"(a1), "r"(a2), "r"(a3), "r"(b0), "r"(b1));
}
__device__ __forceinline__ void lds64(u32& r0, u32& r1, u32 addr) {
    asm volatile("ld.shared.v2.b32 {%0, %1}, [%2];" : "=r"(r0), "=r"(r1) : "r"(addr));
}
__device__ __forceinline__ u32 packh2(float a, float b) {
    __half2 h = __floats2half2_rn(a, b);
    return *(u32*)&h;
}

// ---------------- merged prep kernel ----------------
// blocks [0,2048): weight packing (br = bx>>9); block 0 also decodes indices.
// blocks [2048,6144): x repacking, one block per (b, pb, chunk).
__global__ void prep(const int* __restrict__ yr, const int* __restrict__ ar,
                     const float* __restrict__ x,
                     const float* __restrict__ w0, const float* __restrict__ w1,
                     const float* __restrict__ w2, const float* __restrict__ w3) {
    const int bx = blockIdx.x;
    const int tid = threadIdx.x;

    if (bx == 0) {
        __shared__ int is64;
        if (tid == 0) {
            int acc = 0;
            for (int i = 1; i < NB; i += 2) acc |= yr[i];
            is64 = (acc == 0) ? 1 : 0;
        }
        __syncthreads();
        if (tid < NB) {
            int st = is64 ? 2 : 1;
            g_y[tid]   = yr[tid * st];
            g_arc[tid] = ar[tid * st];
        }
        __syncthreads();
        if (tid == 0) {
            int n = 0;
            for (int br = 3; br >= 0; br--)
                for (int i = 0; i < NB; i++)
                    if (g_arc[i] == br) g_order[n++] = i;
        }
    }

    if (bx < 2048) {
        // ---- weight packing ----
        int br = bx >> 9, gx = bx & 511;
        const float* w = (br == 0) ? w0 : (br == 1) ? w1 : (br == 2) ? w2 : w3;
        int k = 2 * br + 1, kk = k * k;
        int off = c_woffw[br];
        int total = kk * 32768;
        for (int i = gx * 256 + tid; i < total; i += 512 * 256) {
            int rs   = i >> 15;
            int rem  = i & 32767;
            int chunk = rem >> 12;
            int rem3 = rem & 4095;
            int tile = rem3 >> 8;
            int rem4 = rem3 & 255;
            int ks   = rem4 >> 7;
            int rem5 = rem4 & 127;
            int lane = rem5 >> 2, q = rem5 & 3;
            int g = lane >> 2, t = lane & 3;
            int row = tile * 16 + g + ((q & 1) << 3);
            int cl  = t + ((q >> 1) << 2);
            int ch  = chunk * 32 + ks * 16 + cl * 2;
            int base = (row * 256 + ch) * kk + rs;
            g_wf[off + i] = packh2(w[base], w[base + kk]);
        }
    } else {
        // ---- x repacking ----
        __shared__ __half sm[32][132];
        int bid   = bx - 2048;
        int chunk = bid & 7;
        int pb    = (bid >> 3) & 7;
        int b     = bid >> 6;
        for (int j = tid; j < 32 * 128; j += 256) {
            int c = j >> 7, p = j & 127;
            sm[c][p] = __float2half_rn(
                x[(((size_t)b * 256 + chunk * 32 + c) << 10) + pb * 128 + p]);
        }
        __syncthreads();
        for (int j = tid; j < 128 * 16; j += 256) {
            int p = j >> 4, wd = j & 15;
            int ks = wd >> 3, s = wd & 7;
            int cl = (s >> 1) + ((s & 1) << 2);
            int ch = ks * 16 + cl * 2;
            u32 val = packh2(__half2float(sm[ch][p]), __half2float(sm[ch + 1][p]));
            g_xb[((size_t)b << 17) + (size_t)(pb * 128 + p) * 128 + chunk * 16 + wd] = val;
        }
    }
}

// ---------------- main kernel ----------------
// CTA: (b, oct, pband8). 256 thr = 8 warps (4m x 2n), warp tile 32oc x 64pix.
// CTA tile 128oc x 128pix (4 image rows). 2 CTAs/SM. Mainloop templated on K.
#define SMEM_BYTES (2 * 640 * 10 * 4)   // 2 buffers x 640*R_max words = 51200B

template<int K>
__device__ __forceinline__ void mainloop(
    int tid, int lane, int wm, int oct, int pband,
    const u32* xb_img, u32 sb, int woffw,
    const int* pixw, float acc[2][8][4])
{
    constexpr int PK = K / 2;
    constexpr int KK = K * K;
    constexpr int R  = 3 + K;
    constexpr int XW = 640 * R;
    constexpr int NCP  = 160 * R;
    constexpr int T80R = 80 * R;

    const int h0 = pband * 4 - PK;
    const u32 uX[2] = { sb, sb + (u32)XW * 4 };

    #define ISSUE_X(chunk_, ub_) do { \
        _Pragma("unroll 1") \
        for (int id = tid; id < NCP; id += 256) { \
            int ks  = (id >= T80R); \
            int rem = id - ks * T80R; \
            int row = rem / 80; \
            int q_  = rem - row * 80; \
            int col = q_ >> 1, hh = q_ & 1; \
            int hr  = h0 + row, ic = col - 4; \
            bool valid = ((unsigned)hr < HW) && ((unsigned)ic < HW); \
            int pix = valid ? (hr * 32 + ic) : 0; \
            const u32* src = xb_img + (size_t)pix * 128 + (chunk_) * 16 + ks * 8 + hh * 4; \
            u32 dst = (ub_) + (u32)(ks * R * 320 + (row * 40 + col) * 8 + hh * 4) * 4; \
            cpa16(dst, src, valid); \
        } \
    } while (0)

    ISSUE_X(0, uX[0]);
    CP_COMMIT();

    #pragma unroll 1
    for (int chunk = 0; chunk < 8; chunk++) {
        CP_WAIT(0);
        __syncthreads();
        if (chunk < 7) {
            ISSUE_X(chunk + 1, uX[(chunk + 1) & 1]);
            CP_COMMIT();
        }
        const u32 xbuf = uX[chunk & 1];
        const uint4* wchunk = (const uint4*)(g_wf + woffw
            + (size_t)((chunk * 16 + oct * 8 + wm * 2) * 256) + (lane << 2));

        int r = 0, s = 0;
        #pragma unroll 1
        for (int rs = 0; rs < KK; rs++) {
            uint4 a[4];
            const uint4* ap = wchunk + (size_t)rs * 8192;
            #pragma unroll
            for (int j = 0; j < 4; j++)
                a[j] = ap[j * 32];                 // j = mt*2+ks

            const int shiftw = (r * 40 + s - PK + 4) * 8;
            #pragma unroll
            for (int ks = 0; ks < 2; ks++) {
                u32 rb[8][2];
                const u32 bka = xbuf + (u32)(ks * R * 320 + shiftw) * 4;
                #pragma unroll
                for (int nt = 0; nt < 8; nt++)
                    lds64(rb[nt][0], rb[nt][1], bka + (u32)pixw[nt] * 4);
                #pragma unroll
                for (int mt = 0; mt < 2; mt++) {
                    const uint4 av = a[mt * 2 + ks];
                    #pragma unroll
                    for (int nt = 0; nt < 8; nt++)
                        mma_f16(acc[mt][nt], av.x, av.y, av.z, av.w,
                                rb[nt][0], rb[nt][1]);
                }
            }
            if (++s == K) { s = 0; ++r; }
        }
    }
    #undef ISSUE_X
}

__global__ void __launch_bounds__(256, 2)
conv_mma(const float* __restrict__ e0_, const float* __restrict__ e1_,
         const float* __restrict__ e2_, const float* __restrict__ e3_,
         float* __restrict__ out)
{
    extern __shared__ u32 smem[];
    const u32 sb = smem_u32(smem);

    const int tid  = threadIdx.x;
    const int wid  = tid >> 5, lane = tid & 31;
    const int g    = lane >> 2, t = lane & 3;
    const int wm   = wid >> 1;           // 0..3
    const int wn   = wid & 1;            // 0..1

    const int b     = g_order[blockIdx.x >> 4];
    const int oct   = (blockIdx.x >> 3) & 1;
    const int pband = blockIdx.x & 7;    // 4-row band

    const int br = g_arc[b];
    const float* eptr = (br == 0) ? e0_ : (br == 1) ? e1_ : (br == 2) ? e2_ : e3_;
    const int woffw = c_woffw[br];

    int pixw[8];
    #pragma unroll
    for (int nt = 0; nt < 8; nt++) {
        int p = wn * 64 + nt * 8 + g;
        pixw[nt] = ((p >> 5) * 40 + (p & 31)) * 8 + 2 * t;
    }

    float acc[2][8][4];
    #pragma unroll
    for (int mt = 0; mt < 2; mt++)
        #pragma unroll
        for (int nt = 0; nt < 8; nt++)
            #pragma unroll
            for (int q = 0; q < 4; q++)
                acc[mt][nt][q] = 0.0f;

    const u32* xb_img = g_xb + ((size_t)b << 17);

    switch (br) {
        case 0: mainloop<1>(tid, lane, wm, oct, pband, xb_img, sb, woffw, pixw, acc); break;
        case 1: mainloop<3>(tid, lane, wm, oct, pband, xb_img, sb, woffw, pixw, acc); break;
        case 2: mainloop<5>(tid, lane, wm, oct, pband, xb_img, sb, woffw, pixw, acc); break;
        default: mainloop<7>(tid, lane, wm, oct, pband, xb_img, sb, woffw, pixw, acc); break;
    }

    // ---- epilogue: += class embedding, store ----
    const int yb = g_y[b];
    const int ocg = oct * 128 + wm * 32;
    #pragma unroll
    for (int mt = 0; mt < 2; mt++) {
        int oc_lo = ocg + mt * 16 + g;
        int oc_hi = oc_lo + 8;
        float ev_lo = eptr[yb * OUT_C + oc_lo];
        float ev_hi = eptr[yb * OUT_C + oc_hi];
        float* base_lo = out + (size_t)(b * OUT_C + oc_lo) * NPIX + pband * 128;
        float* base_hi = out + (size_t)(b * OUT_C + oc_hi) * NPIX + pband * 128;
        #pragma unroll
        for (int nt = 0; nt < 8; nt++) {
            int p = wn * 64 + nt * 8 + 2 * t;
            float2 vlo = make_float2(acc[mt][nt][0] + ev_lo, acc[mt][nt][1] + ev_lo);
            float2 vhi = make_float2(acc[mt][nt][2] + ev_hi, acc[mt][nt][3] + ev_hi);
            *(float2*)(base_lo + p) = vlo;
            *(float2*)(base_hi + p) = vhi;
        }
    }
}

// ---------------- launcher ----------------
extern "C" void kernel_launch(void* const* d_in, const int* in_sizes, int n_in,
                              void* d_out, int out_size) {
    const float* x = nullptr;
    const int *yr = nullptr, *ar = nullptr;
    const float* w[4] = {nullptr, nullptr, nullptr, nullptr};
    const float* e[4] = {nullptr, nullptr, nullptr, nullptr};
    int ne = 0, n64 = 0;

    for (int i = 0; i < n_in; i++) {
        int sz = in_sizes[i];
        const void* p = d_in[i];
        if      (sz == 16777216) x = (const float*)p;
        else if (sz == 64)       { if (n64++ == 0) yr = (const int*)p; else ar = (const int*)p; }
        else if (sz == 65536)    w[0] = (const float*)p;
        else if (sz == 589824)   w[1] = (const float*)p;
        else if (sz == 1638400)  w[2] = (const float*)p;
        else if (sz == 3211264)  w[3] = (const float*)p;
        else if (sz == 256000)   { if (ne < 4) e[ne++] = (const float*)p; }
    }

    cudaFuncSetAttribute(conv_mma, cudaFuncAttributeMaxDynamicSharedMemorySize, SMEM_BYTES);

    prep<<<6144, 256>>>(yr, ar, x, w[0], w[1], w[2], w[3]);
    conv_mma<<<1024, 256, SMEM_BYTES>>>(e[0], e[1], e[2], e[3], (float*)d_out);
}